// round 11
// baseline (speedup 1.0000x reference)
#include <cuda_runtime.h>
#include <cuda_fp16.h>
#include <math.h>

#define T_STEPS 256
#define B_SZ    64
#define H_SZ    1024
#define O_SZ    1024
#define BH      (B_SZ * H_SZ)        // 65536
#define M_TOT   (T_STEPS * B_SZ)     // 16384
#define NCTA    128
#define PAD     40                   // smem row stride (fp16 elems), big gemms
#define RPAD    136                  // smem row stride (fp16 elems), rec h chunks
#define WPAD    1032                 // smem row stride (fp16 elems), rec Wh rows

typedef unsigned long long u64;
typedef unsigned int u32;

__device__ __forceinline__ u32 smem_u32(const void* p) {
    u32 a; asm("{ .reg .u64 t; cvta.to.shared.u64 t, %1; cvt.u32.u64 %0, t; }"
               : "=r"(a) : "l"(p));
    return a;
}

// ---- cp.async helpers ------------------------------------------------------
__device__ __forceinline__ void cp16(u32 dst, const void* src) {
    asm volatile("cp.async.cg.shared.global [%0], [%1], 16;"
                 :: "r"(dst), "l"(src));
}
#define CP_COMMIT() asm volatile("cp.async.commit_group;" ::: "memory")
#define CP_WAIT0()  asm volatile("cp.async.wait_group 0;" ::: "memory")

// ---- mma.sync helpers ------------------------------------------------------
__device__ __forceinline__ void ldmx4(u32& r0, u32& r1, u32& r2, u32& r3, u32 a) {
    asm volatile("ldmatrix.sync.aligned.m8n8.x4.shared.b16 {%0,%1,%2,%3}, [%4];"
                 : "=r"(r0), "=r"(r1), "=r"(r2), "=r"(r3) : "r"(a));
}
__device__ __forceinline__ void ldmx2(u32& r0, u32& r1, u32 a) {
    asm volatile("ldmatrix.sync.aligned.m8n8.x2.shared.b16 {%0,%1}, [%2];"
                 : "=r"(r0), "=r"(r1) : "r"(a));
}
__device__ __forceinline__ void mma_f16(float* c, const u32* a, const u32* b) {
    asm volatile(
        "mma.sync.aligned.m16n8k16.row.col.f32.f16.f16.f32 "
        "{%0,%1,%2,%3}, {%4,%5,%6,%7}, {%8,%9}, {%0,%1,%2,%3};"
        : "+f"(c[0]), "+f"(c[1]), "+f"(c[2]), "+f"(c[3])
        : "r"(a[0]), "r"(a[1]), "r"(a[2]), "r"(a[3]), "r"(b[0]), "r"(b[1]));
}

// ---- scratch ---------------------------------------------------------------
__device__ float g_acc[(size_t)M_TOT * H_SZ];      // ix + bi + bh (fp32)
__device__ __half g_A1f[(size_t)M_TOT * H_SZ];     // gathered emb, single fp16
__device__ __half g_hsf[(size_t)M_TOT * H_SZ];     // h states, single fp16
__device__ __half g_h0f[BH];
__device__ __half g_WiThf[(size_t)H_SZ * H_SZ];    // fp16 hi/lo [n][k]
__device__ __half g_WiTlf[(size_t)H_SZ * H_SZ];
__device__ __half g_WoThf[(size_t)H_SZ * O_SZ];
__device__ __half g_WoTlf[(size_t)H_SZ * O_SZ];
__device__ __half g_WhThf[(size_t)H_SZ * H_SZ];
__device__ __half g_WhTlf[(size_t)H_SZ * H_SZ];
__device__ float g_bias1[H_SZ];
__device__ unsigned g_cnt[2];
__device__ unsigned g_flag[2];
__device__ u32 g_stepf2[NCTA];                     // per-CTA progress flags

// ---------------------------------------------------------------------------
// Prep kernels
// ---------------------------------------------------------------------------
__global__ void prep_bias(const float* __restrict__ bi, const float* __restrict__ bh) {
    int i = blockIdx.x * 256 + threadIdx.x;
    g_bias1[i] = bi[i] + bh[i];
}

// W=0: Wi, W=1: Wo, W=2: Wh -> fp16 hi/lo [n][k]
template<int W>
__global__ void prep_transpose_f16(const float* __restrict__ src) {
    __shared__ float ts[32][33];
    __half* dhi = (W == 0) ? g_WiThf : (W == 1) ? g_WoThf : g_WhThf;
    __half* dlo = (W == 0) ? g_WiTlf : (W == 1) ? g_WoTlf : g_WhTlf;
    int n0 = blockIdx.x * 32, k0 = blockIdx.y * 32;
    int tx = threadIdx.x & 31, ty = threadIdx.x >> 5;
#pragma unroll
    for (int i = 0; i < 4; i++)
        ts[ty + i * 8][tx] = src[(size_t)(k0 + ty + i * 8) * H_SZ + n0 + tx];
    __syncthreads();
#pragma unroll
    for (int i = 0; i < 4; i++) {
        int n = n0 + ty + i * 8;
        float v = ts[tx][ty + i * 8];
        __half h = __float2half_rn(v);
        float r = v - __half2float(h);
        dhi[(size_t)n * H_SZ + k0 + tx] = h;
        dlo[(size_t)n * H_SZ + k0 + tx] = __float2half_rn(r);
    }
}

__global__ void prep_gather(const int* __restrict__ input, const float* __restrict__ emb) {
    size_t g = (size_t)blockIdx.x * 256 + threadIdx.x;
    size_t e = g * 8;
    int m = (int)(e >> 10), k = (int)(e & 1023);
    int t = m >> 6, b = m & 63;
    int row = input[b * T_STEPS + t];
    float4 v0 = *(const float4*)(emb + (size_t)row * H_SZ + k);
    float4 v1 = *(const float4*)(emb + (size_t)row * H_SZ + k + 4);
    __half hh[8] = {__float2half_rn(v0.x), __float2half_rn(v0.y),
                    __float2half_rn(v0.z), __float2half_rn(v0.w),
                    __float2half_rn(v1.x), __float2half_rn(v1.y),
                    __float2half_rn(v1.z), __float2half_rn(v1.w)};
    *(uint4*)(g_A1f + e) = *(uint4*)hh;
}

__global__ void prep_h0(const float* __restrict__ hidden0) {
    size_t e = ((size_t)blockIdx.x * 256 + threadIdx.x) * 4;
    float4 v = *(const float4*)(hidden0 + e);
    __half hh[4] = {__float2half_rn(v.x), __float2half_rn(v.y),
                    __float2half_rn(v.z), __float2half_rn(v.w)};
    *(uint2*)(g_h0f + e) = *(uint2*)hh;
}

// ---------------------------------------------------------------------------
// fp16 2-term mma GEMM (proven R10 structure), 128x128 CTA tile.
// MODE 0: A=g_A1f,  B=WiT,  dst=g_acc (+g_bias1)
// MODE 1: A=g_hsf,  B=WoT,  dst=out [b][t] remap (+bo)
// ---------------------------------------------------------------------------
#define TILE_BF (128 * PAD)
#define SMEM_G (2 * 3 * TILE_BF * 2)

template<int MODE>
__global__ __launch_bounds__(256) void gemm_f16(const float* __restrict__ bias_ext,
                                                float* __restrict__ dst_ext)
{
    extern __shared__ __half smh[];
    const int tid = threadIdx.x, wid = tid >> 5, lane = tid & 31;
    const int nt = blockIdx.x, mt = blockIdx.y;
    const int wm = wid >> 1, wn = wid & 1;

    const __half* A  = MODE ? g_hsf   : g_A1f;
    const __half* Bh = MODE ? g_WoThf : g_WiThf;
    const __half* Bl = MODE ? g_WoTlf : g_WiTlf;
    const float* bias = MODE ? bias_ext : g_bias1;

    const __half* srcT[3] = { A  + (size_t)mt * 128 * H_SZ,
                              Bh + (size_t)nt * 128 * H_SZ,
                              Bl + (size_t)nt * 128 * H_SZ };

    const int r0 = tid >> 2, q0 = tid & 3;
    const int r1 = r0 + 64;
    const u32 sbase = smem_u32(smh);

#pragma unroll
    for (int t4 = 0; t4 < 3; t4++) {
        const __half* s = srcT[t4];
        u32 d = sbase + (u32)(t4 * TILE_BF) * 2;
        cp16(d + (u32)(r0 * PAD + q0 * 8) * 2, s + (size_t)r0 * H_SZ + q0 * 8);
        cp16(d + (u32)(r1 * PAD + q0 * 8) * 2, s + (size_t)r1 * H_SZ + q0 * 8);
    }
    CP_COMMIT(); CP_WAIT0();
    __syncthreads();

    float acc[2][8][4];
#pragma unroll
    for (int mi = 0; mi < 2; mi++)
#pragma unroll
        for (int j = 0; j < 8; j++)
#pragma unroll
            for (int v = 0; v < 4; v++) acc[mi][j][v] = 0.f;

    const int a_row = lane & 15, a_kq = lane >> 4;
    const int b_nr = (lane >> 4) * 8 + (lane & 7), b_kq = (lane >> 3) & 1;

#pragma unroll 1
    for (int c = 0; c < 32; c++) {
        const int buf = c & 1;
        if (c < 31) {
            const int col0 = (c + 1) * 32;
#pragma unroll
            for (int t4 = 0; t4 < 3; t4++) {
                const __half* s = srcT[t4] + col0;
                u32 d = sbase + (u32)(((buf ^ 1) * 3 + t4) * TILE_BF) * 2;
                cp16(d + (u32)(r0 * PAD + q0 * 8) * 2, s + (size_t)r0 * H_SZ + q0 * 8);
                cp16(d + (u32)(r1 * PAD + q0 * 8) * 2, s + (size_t)r1 * H_SZ + q0 * 8);
            }
            CP_COMMIT();
        }

        const u32 bA = sbase + (u32)(buf * 3) * TILE_BF * 2;
#pragma unroll
        for (int s = 0; s < 2; s++) {
            const int kc0 = s * 16;
            u32 a[2][4], bhi[8][2], blo[8][2];
#pragma unroll
            for (int mi = 0; mi < 2; mi++) {
                u32 off = (u32)((wm * 32 + mi * 16 + a_row) * PAD + kc0 + a_kq * 8) * 2;
                ldmx4(a[mi][0], a[mi][1], a[mi][2], a[mi][3], bA + 0 * TILE_BF * 2 + off);
            }
#pragma unroll
            for (int ni = 0; ni < 4; ni++) {
                u32 off = (u32)((wn * 64 + ni * 16 + b_nr) * PAD + kc0 + b_kq * 8) * 2;
                ldmx4(bhi[2*ni][0], bhi[2*ni][1], bhi[2*ni+1][0], bhi[2*ni+1][1],
                      bA + 1 * TILE_BF * 2 + off);
                ldmx4(blo[2*ni][0], blo[2*ni][1], blo[2*ni+1][0], blo[2*ni+1][1],
                      bA + 2 * TILE_BF * 2 + off);
            }
#pragma unroll
            for (int mi = 0; mi < 2; mi++)
#pragma unroll
                for (int j = 0; j < 8; j++) {
                    mma_f16(acc[mi][j], a[mi], bhi[j]);
                    mma_f16(acc[mi][j], a[mi], blo[j]);
                }
        }
        if (c < 31) CP_WAIT0();
        __syncthreads();
    }

    const int gid = lane >> 2, qid = lane & 3;
#pragma unroll
    for (int mi = 0; mi < 2; mi++) {
#pragma unroll
        for (int j = 0; j < 8; j++) {
            int col = nt * 128 + wn * 64 + j * 8 + qid * 2;
            float2 bv = *(const float2*)(bias + col);
            int mA = mt * 128 + wm * 32 + mi * 16 + gid;
            int mB = mA + 8;
            float* dA; float* dB;
            if (MODE == 0) {
                dA = g_acc + (size_t)mA * H_SZ + col;
                dB = g_acc + (size_t)mB * H_SZ + col;
            } else {
                dA = dst_ext + ((size_t)(mA & 63) * T_STEPS + (mA >> 6)) * O_SZ + col;
                dB = dst_ext + ((size_t)(mB & 63) * T_STEPS + (mB >> 6)) * O_SZ + col;
            }
            *(float2*)dA = make_float2(acc[mi][j][0] + bv.x, acc[mi][j][1] + bv.y);
            *(float2*)dB = make_float2(acc[mi][j][2] + bv.x, acc[mi][j][3] + bv.y);
        }
    }
}

// ---------------------------------------------------------------------------
// Flat grid barrier (proven). Used ONCE at end of rec for flag reset.
// ---------------------------------------------------------------------------
__device__ __forceinline__ void grid_barrier(int slot) {
    __syncthreads();
    if (threadIdx.x == 0) {
        volatile unsigned* fl = &g_flag[slot];
        unsigned prev = *fl;
        __threadfence();
        unsigned old = atomicAdd(&g_cnt[slot], 1u);
        if (old == NCTA - 1) {
            atomicExch(&g_cnt[slot], 0u);
            __threadfence();
            atomicAdd(&g_flag[slot], 1u);
        } else {
            while (*fl == prev) { }
        }
        __threadfence();
    }
    __syncthreads();
}

// ---------------------------------------------------------------------------
// Persistent recurrence v2: NO k-split across CTAs.
// 128 CTAs; CTA ct owns output cols ct*8..+8 over FULL K=1024.
// K split across 8 warps (warp w: k16 index w of each 128-k chunk).
// Wh rows (8 x 1024, fp16 hi/lo) resident in smem; h(t-1) streamed in 8
// chunks of 64x128 fp16, double-buffered cp.async overlapped with mma.
// Cross-warp reduce in smem, then tanh + fp16 h store + flag publish.
// ---------------------------------------------------------------------------
#define SM_WHI 0
#define SM_WLO 16512
#define SM_A0  33024
#define SM_A1  50432
#define SM_RED 67840
#define SMEM_REC2 84224

__global__ __launch_bounds__(256) void rec_mma2(float* __restrict__ hid_out)
{
    extern __shared__ char rsm[];
    const u32 sbase = smem_u32(rsm);
    const int tid = threadIdx.x, wid = tid >> 5, lane = tid & 31;
    const int ct = blockIdx.x;

    // one-time Wh rows load: n = ct*8..+8, k = 0..1024, hi+lo
#pragma unroll
    for (int i = 0; i < 4; i++) {
        int ch = tid + i * 256;           // 0..1023
        int r  = ch >> 7;                 // 0..7
        int co = (ch & 127) * 8;          // 0..1016
        size_t src = (size_t)(ct * 8 + r) * H_SZ + co;
        *(uint4*)(rsm + SM_WHI + (r * WPAD + co) * 2) = *(const uint4*)(g_WhThf + src);
        *(uint4*)(rsm + SM_WLO + (r * WPAD + co) * 2) = *(const uint4*)(g_WhTlf + src);
    }

    const int a_row = lane & 15, a_kq = lane >> 4;
    const int b_nr = (lane >> 4) * 8 + (lane & 7), b_kq = (lane >> 3) & 1;
    const int gid = lane >> 2, qid = lane & 3;

    // reduce mapping: thread owns (row r, cols ct*8 + cp2, cp2+1)
    const int red_r  = tid >> 2;
    const int red_cp = (tid & 3) * 2;
    const size_t red_off = (size_t)red_r * H_SZ + ct * 8 + red_cp;

    float* red = (float*)(rsm + SM_RED);   // [8 warps][64 rows][8 cols]

#pragma unroll 1
    for (int t = 0; t < T_STEPS; t++) {
        const __half* hsrc = t ? (g_hsf + (size_t)(t - 1) * BH) : g_h0f;

        float2 aacc = *(const float2*)(g_acc + (size_t)t * BH + red_off);

        // wait for all producers of h(t-1)
        if (t > 0) {
            if (tid < NCTA) {
                volatile u32* f = &g_stepf2[tid];
                while (*f < (u32)t) { }
                __threadfence();
            }
            __syncthreads();
        }

        // stage chunk 0
#pragma unroll
        for (int i = 0; i < 4; i++) {
            int ch = tid + i * 256;
            int r  = ch >> 4;
            int co = (ch & 15) * 8;
            cp16(sbase + (u32)(SM_A0 + (r * RPAD + co) * 2),
                 hsrc + (size_t)r * H_SZ + co);
        }
        CP_COMMIT(); CP_WAIT0();
        __syncthreads();

        float acc[4][4];
#pragma unroll
        for (int mi = 0; mi < 4; mi++)
#pragma unroll
            for (int v = 0; v < 4; v++) acc[mi][v] = 0.f;

#pragma unroll 1
        for (int c = 0; c < 8; c++) {
            if (c < 7) {
                u32 dbase = sbase + (u32)(((c + 1) & 1) ? SM_A1 : SM_A0);
#pragma unroll
                for (int i = 0; i < 4; i++) {
                    int ch = tid + i * 256;
                    int r  = ch >> 4;
                    int co = (ch & 15) * 8;
                    cp16(dbase + (u32)((r * RPAD + co) * 2),
                         hsrc + (size_t)r * H_SZ + (c + 1) * 128 + co);
                }
                CP_COMMIT();
            }

            const u32 abase = sbase + (u32)((c & 1) ? SM_A1 : SM_A0);
            const int kofs = wid * 16;          // this warp's k16 within chunk
            u32 a[4][4], bh[2], bl[2];
#pragma unroll
            for (int mi = 0; mi < 4; mi++) {
                u32 off = (u32)((mi * 16 + a_row) * RPAD + kofs + a_kq * 8) * 2;
                ldmx4(a[mi][0], a[mi][1], a[mi][2], a[mi][3], abase + off);
            }
            {
                u32 off = (u32)(b_nr * WPAD + c * 128 + kofs + b_kq * 8) * 2;
                ldmx2(bh[0], bh[1], sbase + SM_WHI + off);
                ldmx2(bl[0], bl[1], sbase + SM_WLO + off);
            }
#pragma unroll
            for (int mi = 0; mi < 4; mi++) {
                mma_f16(acc[mi], a[mi], bh);
                mma_f16(acc[mi], a[mi], bl);
            }

            if (c < 7) CP_WAIT0();
            __syncthreads();
        }

        // cross-warp reduce: warp partials -> smem
#pragma unroll
        for (int mi = 0; mi < 4; mi++) {
            int row = mi * 16 + gid;
            *(float2*)&red[((size_t)wid * 64 + row) * 8 + qid * 2] =
                make_float2(acc[mi][0], acc[mi][1]);
            *(float2*)&red[((size_t)wid * 64 + row + 8) * 8 + qid * 2] =
                make_float2(acc[mi][2], acc[mi][3]);
        }
        __syncthreads();

        // final: sum 8 warps + pre-activation, tanh, fp16 store
        {
            float2 a2 = aacc;
#pragma unroll
            for (int p = 0; p < 8; p++) {
                float2 q = *(const float2*)&red[((size_t)p * 64 + red_r) * 8 + red_cp];
                a2.x += q.x; a2.y += q.y;
            }
            a2.x = tanhf(a2.x); a2.y = tanhf(a2.y);

            __half h0 = __float2half_rn(a2.x), h1 = __float2half_rn(a2.y);
            u32 packed = (u32)__half_as_ushort(h0) | ((u32)__half_as_ushort(h1) << 16);
            *(u32*)(g_hsf + (size_t)t * BH + red_off) = packed;

            if (hid_out && t == T_STEPS - 1)
                *(float2*)(hid_out + red_off) = a2;
        }

        __threadfence();
        __syncthreads();
        if (tid == 0)
            *(volatile u32*)&g_stepf2[ct] = (u32)(t + 1);
    }

    // reset flags for graph replay (behind a full grid barrier)
    grid_barrier(0);
    if (blockIdx.x == 0 && tid < NCTA) g_stepf2[tid] = 0;
}

// ---------------------------------------------------------------------------
extern "C" void kernel_launch(void* const* d_in, const int* in_sizes, int n_in,
                              void* d_out, int out_size)
{
    const int*   input   = (const int*)  d_in[0];
    const float* hidden0 = (const float*)d_in[1];
    const float* emb     = (const float*)d_in[2];
    const float* Wi      = (const float*)d_in[3];
    const float* bi      = (const float*)d_in[4];
    const float* Wh      = (const float*)d_in[5];
    const float* bh      = (const float*)d_in[6];
    const float* Wo      = (const float*)d_in[7];
    const float* bo      = (const float*)d_in[8];
    float* out = (float*)d_out;

    float* hid_out = (out_size >= M_TOT * O_SZ + BH) ? out + (size_t)M_TOT * O_SZ
                                                     : (float*)0;

    cudaFuncSetAttribute(gemm_f16<0>, cudaFuncAttributeMaxDynamicSharedMemorySize, SMEM_G);
    cudaFuncSetAttribute(gemm_f16<1>, cudaFuncAttributeMaxDynamicSharedMemorySize, SMEM_G);
    cudaFuncSetAttribute(rec_mma2,   cudaFuncAttributeMaxDynamicSharedMemorySize, SMEM_REC2);

    prep_bias<<<4, 256>>>(bi, bh);
    prep_transpose_f16<0><<<dim3(32, 32), 256>>>(Wi);
    prep_transpose_f16<1><<<dim3(32, 32), 256>>>(Wo);
    prep_transpose_f16<2><<<dim3(32, 32), 256>>>(Wh);
    prep_h0<<<64, 256>>>(hidden0);
    prep_gather<<<8192, 256>>>(input, emb);

    gemm_f16<0><<<dim3(8, 128), 256, SMEM_G>>>((const float*)0, (float*)0);
    rec_mma2<<<NCTA, 256, SMEM_REC2>>>(hid_out);
    gemm_f16<1><<<dim3(8, 128), 256, SMEM_G>>>(bo, out);
}

// round 12
// speedup vs baseline: 1.7182x; 1.7182x over previous
#include <cuda_runtime.h>
#include <cuda_fp16.h>
#include <math.h>

#define T_STEPS 256
#define B_SZ    64
#define H_SZ    1024
#define O_SZ    1024
#define BH      (B_SZ * H_SZ)        // 65536
#define M_TOT   (T_STEPS * B_SZ)     // 16384
#define KSPLIT  8                    // recurrence k-split == cluster size
#define NCTA    128
#define PAD     40                   // smem row stride (fp16 elems), big gemms
#define RPAD    136                  // smem row stride (fp16 elems), rec tiles

typedef unsigned long long u64;
typedef unsigned int u32;

__device__ __forceinline__ u32 smem_u32(const void* p) {
    u32 a; asm("{ .reg .u64 t; cvta.to.shared.u64 t, %1; cvt.u32.u64 %0, t; }"
               : "=r"(a) : "l"(p));
    return a;
}

// ---- cp.async helpers ------------------------------------------------------
__device__ __forceinline__ void cp16(u32 dst, const void* src) {
    asm volatile("cp.async.cg.shared.global [%0], [%1], 16;"
                 :: "r"(dst), "l"(src));
}
#define CP_COMMIT() asm volatile("cp.async.commit_group;" ::: "memory")
#define CP_WAIT0()  asm volatile("cp.async.wait_group 0;" ::: "memory")

// ---- mma.sync helpers ------------------------------------------------------
__device__ __forceinline__ void ldmx4(u32& r0, u32& r1, u32& r2, u32& r3, u32 a) {
    asm volatile("ldmatrix.sync.aligned.m8n8.x4.shared.b16 {%0,%1,%2,%3}, [%4];"
                 : "=r"(r0), "=r"(r1), "=r"(r2), "=r"(r3) : "r"(a));
}
__device__ __forceinline__ void mma_f16(float* c, const u32* a, const u32* b) {
    asm volatile(
        "mma.sync.aligned.m16n8k16.row.col.f32.f16.f16.f32 "
        "{%0,%1,%2,%3}, {%4,%5,%6,%7}, {%8,%9}, {%0,%1,%2,%3};"
        : "+f"(c[0]), "+f"(c[1]), "+f"(c[2]), "+f"(c[3])
        : "r"(a[0]), "r"(a[1]), "r"(a[2]), "r"(a[3]), "r"(b[0]), "r"(b[1]));
}

// ---- scratch ---------------------------------------------------------------
__device__ float g_acc[(size_t)M_TOT * H_SZ];      // ix + bi + bh (fp32)
__device__ __half g_A1f[(size_t)M_TOT * H_SZ];     // gathered emb, single fp16
__device__ __half g_hsf[(size_t)M_TOT * H_SZ];     // h states, single fp16
__device__ __half g_h0f[BH];
__device__ __half g_WiThf[(size_t)H_SZ * H_SZ];    // fp16 hi/lo [n][k]
__device__ __half g_WiTlf[(size_t)H_SZ * H_SZ];
__device__ __half g_WoThf[(size_t)H_SZ * O_SZ];
__device__ __half g_WoTlf[(size_t)H_SZ * O_SZ];
__device__ __half g_WhThf[(size_t)H_SZ * H_SZ];
__device__ __half g_WhTlf[(size_t)H_SZ * H_SZ];
__device__ float g_parts[2][(size_t)KSPLIT * BH];  // double-buffered by t&1
__device__ float g_bias1[H_SZ];
__device__ unsigned g_cnt[2];
__device__ unsigned g_flag[2];
__device__ u32 g_stepf[16][8];                     // per-(chunk, kc) flags

// ---------------------------------------------------------------------------
// Prep kernels
// ---------------------------------------------------------------------------
__global__ void prep_bias(const float* __restrict__ bi, const float* __restrict__ bh) {
    int i = blockIdx.x * 256 + threadIdx.x;
    g_bias1[i] = bi[i] + bh[i];
}

// W=0: Wi, W=1: Wo, W=2: Wh -> fp16 hi/lo [n][k]
template<int W>
__global__ void prep_transpose_f16(const float* __restrict__ src) {
    __shared__ float ts[32][33];
    __half* dhi = (W == 0) ? g_WiThf : (W == 1) ? g_WoThf : g_WhThf;
    __half* dlo = (W == 0) ? g_WiTlf : (W == 1) ? g_WoTlf : g_WhTlf;
    int n0 = blockIdx.x * 32, k0 = blockIdx.y * 32;
    int tx = threadIdx.x & 31, ty = threadIdx.x >> 5;
#pragma unroll
    for (int i = 0; i < 4; i++)
        ts[ty + i * 8][tx] = src[(size_t)(k0 + ty + i * 8) * H_SZ + n0 + tx];
    __syncthreads();
#pragma unroll
    for (int i = 0; i < 4; i++) {
        int n = n0 + ty + i * 8;
        float v = ts[tx][ty + i * 8];
        __half h = __float2half_rn(v);
        float r = v - __half2float(h);
        dhi[(size_t)n * H_SZ + k0 + tx] = h;
        dlo[(size_t)n * H_SZ + k0 + tx] = __float2half_rn(r);
    }
}

__global__ void prep_gather(const int* __restrict__ input, const float* __restrict__ emb) {
    size_t g = (size_t)blockIdx.x * 256 + threadIdx.x;
    size_t e = g * 8;
    int m = (int)(e >> 10), k = (int)(e & 1023);
    int t = m >> 6, b = m & 63;
    int row = input[b * T_STEPS + t];
    float4 v0 = *(const float4*)(emb + (size_t)row * H_SZ + k);
    float4 v1 = *(const float4*)(emb + (size_t)row * H_SZ + k + 4);
    __half hh[8] = {__float2half_rn(v0.x), __float2half_rn(v0.y),
                    __float2half_rn(v0.z), __float2half_rn(v0.w),
                    __float2half_rn(v1.x), __float2half_rn(v1.y),
                    __float2half_rn(v1.z), __float2half_rn(v1.w)};
    *(uint4*)(g_A1f + e) = *(uint4*)hh;
}

__global__ void prep_h0(const float* __restrict__ hidden0) {
    size_t e = ((size_t)blockIdx.x * 256 + threadIdx.x) * 4;
    float4 v = *(const float4*)(hidden0 + e);
    __half hh[4] = {__float2half_rn(v.x), __float2half_rn(v.y),
                    __float2half_rn(v.z), __float2half_rn(v.w)};
    *(uint2*)(g_h0f + e) = *(uint2*)hh;
}

// ---------------------------------------------------------------------------
// fp16 2-term mma GEMM (proven R10/R11 structure), 128x128 CTA tile.
// MODE 0: A=g_A1f,  B=WiT,  dst=g_acc (+g_bias1)
// MODE 1: A=g_hsf,  B=WoT,  dst=out [b][t] remap (+bo)
// ---------------------------------------------------------------------------
#define TILE_BF (128 * PAD)
#define SMEM_G (2 * 3 * TILE_BF * 2)

template<int MODE>
__global__ __launch_bounds__(256) void gemm_f16(const float* __restrict__ bias_ext,
                                                float* __restrict__ dst_ext)
{
    extern __shared__ __half smh[];
    const int tid = threadIdx.x, wid = tid >> 5, lane = tid & 31;
    const int nt = blockIdx.x, mt = blockIdx.y;
    const int wm = wid >> 1, wn = wid & 1;

    const __half* A  = MODE ? g_hsf   : g_A1f;
    const __half* Bh = MODE ? g_WoThf : g_WiThf;
    const __half* Bl = MODE ? g_WoTlf : g_WiTlf;
    const float* bias = MODE ? bias_ext : g_bias1;

    const __half* srcT[3] = { A  + (size_t)mt * 128 * H_SZ,
                              Bh + (size_t)nt * 128 * H_SZ,
                              Bl + (size_t)nt * 128 * H_SZ };

    const int r0 = tid >> 2, q0 = tid & 3;
    const int r1 = r0 + 64;
    const u32 sbase = smem_u32(smh);

#pragma unroll
    for (int t4 = 0; t4 < 3; t4++) {
        const __half* s = srcT[t4];
        u32 d = sbase + (u32)(t4 * TILE_BF) * 2;
        cp16(d + (u32)(r0 * PAD + q0 * 8) * 2, s + (size_t)r0 * H_SZ + q0 * 8);
        cp16(d + (u32)(r1 * PAD + q0 * 8) * 2, s + (size_t)r1 * H_SZ + q0 * 8);
    }
    CP_COMMIT(); CP_WAIT0();
    __syncthreads();

    float acc[2][8][4];
#pragma unroll
    for (int mi = 0; mi < 2; mi++)
#pragma unroll
        for (int j = 0; j < 8; j++)
#pragma unroll
            for (int v = 0; v < 4; v++) acc[mi][j][v] = 0.f;

    const int a_row = lane & 15, a_kq = lane >> 4;
    const int b_nr = (lane >> 4) * 8 + (lane & 7), b_kq = (lane >> 3) & 1;

#pragma unroll 1
    for (int c = 0; c < 32; c++) {
        const int buf = c & 1;
        if (c < 31) {
            const int col0 = (c + 1) * 32;
#pragma unroll
            for (int t4 = 0; t4 < 3; t4++) {
                const __half* s = srcT[t4] + col0;
                u32 d = sbase + (u32)(((buf ^ 1) * 3 + t4) * TILE_BF) * 2;
                cp16(d + (u32)(r0 * PAD + q0 * 8) * 2, s + (size_t)r0 * H_SZ + q0 * 8);
                cp16(d + (u32)(r1 * PAD + q0 * 8) * 2, s + (size_t)r1 * H_SZ + q0 * 8);
            }
            CP_COMMIT();
        }

        const u32 bA = sbase + (u32)(buf * 3) * TILE_BF * 2;
#pragma unroll
        for (int s = 0; s < 2; s++) {
            const int kc0 = s * 16;
            u32 a[2][4], bhi[8][2], blo[8][2];
#pragma unroll
            for (int mi = 0; mi < 2; mi++) {
                u32 off = (u32)((wm * 32 + mi * 16 + a_row) * PAD + kc0 + a_kq * 8) * 2;
                ldmx4(a[mi][0], a[mi][1], a[mi][2], a[mi][3], bA + 0 * TILE_BF * 2 + off);
            }
#pragma unroll
            for (int ni = 0; ni < 4; ni++) {
                u32 off = (u32)((wn * 64 + ni * 16 + b_nr) * PAD + kc0 + b_kq * 8) * 2;
                ldmx4(bhi[2*ni][0], bhi[2*ni][1], bhi[2*ni+1][0], bhi[2*ni+1][1],
                      bA + 1 * TILE_BF * 2 + off);
                ldmx4(blo[2*ni][0], blo[2*ni][1], blo[2*ni+1][0], blo[2*ni+1][1],
                      bA + 2 * TILE_BF * 2 + off);
            }
#pragma unroll
            for (int mi = 0; mi < 2; mi++)
#pragma unroll
                for (int j = 0; j < 8; j++) {
                    mma_f16(acc[mi][j], a[mi], bhi[j]);
                    mma_f16(acc[mi][j], a[mi], blo[j]);
                }
        }
        if (c < 31) CP_WAIT0();
        __syncthreads();
    }

    const int gid = lane >> 2, qid = lane & 3;
#pragma unroll
    for (int mi = 0; mi < 2; mi++) {
#pragma unroll
        for (int j = 0; j < 8; j++) {
            int col = nt * 128 + wn * 64 + j * 8 + qid * 2;
            float2 bv = *(const float2*)(bias + col);
            int mA = mt * 128 + wm * 32 + mi * 16 + gid;
            int mB = mA + 8;
            float* dA; float* dB;
            if (MODE == 0) {
                dA = g_acc + (size_t)mA * H_SZ + col;
                dB = g_acc + (size_t)mB * H_SZ + col;
            } else {
                dA = dst_ext + ((size_t)(mA & 63) * T_STEPS + (mA >> 6)) * O_SZ + col;
                dB = dst_ext + ((size_t)(mB & 63) * T_STEPS + (mB >> 6)) * O_SZ + col;
            }
            *(float2*)dA = make_float2(acc[mi][j][0] + bv.x, acc[mi][j][1] + bv.y);
            *(float2*)dB = make_float2(acc[mi][j][2] + bv.x, acc[mi][j][3] + bv.y);
        }
    }
}

// ---------------------------------------------------------------------------
// Flat grid barrier (proven). Used ONCE at end of rec for flag reset.
// ---------------------------------------------------------------------------
__device__ __forceinline__ void grid_barrier(int slot) {
    __syncthreads();
    if (threadIdx.x == 0) {
        volatile unsigned* fl = &g_flag[slot];
        unsigned prev = *fl;
        __threadfence();
        unsigned old = atomicAdd(&g_cnt[slot], 1u);
        if (old == NCTA - 1) {
            atomicExch(&g_cnt[slot], 0u);
            __threadfence();
            atomicAdd(&g_flag[slot], 1u);
        } else {
            while (*fl == prev) { }
        }
        __threadfence();
    }
    __syncthreads();
}

// ---------------------------------------------------------------------------
// Persistent recurrence (R10-proven): clustered k-split, flag-pipelined,
// fp16 2-term. ct = blockIdx.x >> 3, kc = blockIdx.x & 7.
// ---------------------------------------------------------------------------
#define R_WHI 0
#define R_WLO (64 * RPAD)
#define R_A   (2 * 64 * RPAD)
#define SMEM_REC_BYTES (3 * 64 * RPAD * 2)

__global__ __launch_bounds__(256) __cluster_dims__(KSPLIT, 1, 1)
void rec_mma(float* __restrict__ hid_out)
{
    extern __shared__ __half rsh[];
    const int tid = threadIdx.x, wid = tid >> 5, lane = tid & 31;
    const int ct  = blockIdx.x >> 3;
    const int kc  = blockIdx.x & 7;
    const int wm  = wid >> 1, wn = wid & 1;

    // one-time Wh tile load: rows n = ct*64 .. +64, cols k = kc*128 .. +128
    {
        const size_t base = (size_t)(ct * 64) * H_SZ + kc * 128;
#pragma unroll
        for (int i = 0; i < 4; i++) {
            int ch = tid + i * 256;
            int r  = ch >> 4;
            int co = (ch & 15) * 8;
            *(uint4*)(rsh + R_WHI + r * RPAD + co) =
                *(const uint4*)(g_WhThf + base + (size_t)r * H_SZ + co);
            *(uint4*)(rsh + R_WLO + r * RPAD + co) =
                *(const uint4*)(g_WhTlf + base + (size_t)r * H_SZ + co);
        }
    }

    const u32 sbase = smem_u32(rsh);
    const int a_row = lane & 15, a_kq = lane >> 4;
    const int b_nr = (lane >> 4) * 8 + (lane & 7), b_kq = (lane >> 3) & 1;
    const int gid = lane >> 2, qid = lane & 3;

    // reduce mapping: rows kc*8 + (tid>>5), cols ct*64 + (tid&31)*2
    const int red_row = kc * 8 + (tid >> 5);
    const size_t red_off = (size_t)red_row * H_SZ + ct * 64 + (tid & 31) * 2;

    volatile u32* myflag = (tid < 16)
        ? &g_stepf[2 * kc + (tid >> 3)][tid & 7] : (volatile u32*)0;

#pragma unroll 1
    for (int t = 0; t < T_STEPS; t++) {
        const __half* hsrc = t ? (g_hsf + (size_t)(t - 1) * BH) : g_h0f;
        float* parts = g_parts[t & 1];

        float2 aacc = *(const float2*)(g_acc + (size_t)t * BH + red_off);

        if (t > 0) {
            if (tid < 16) {
                while (*myflag < (u32)t) { }
                __threadfence();
            }
            __syncthreads();
        }

        // stage h slice (64 x 128 fp16 = 16KB) via cp.async
#pragma unroll
        for (int i = 0; i < 4; i++) {
            int ch = tid + i * 256;
            int r  = ch >> 4;
            int co = (ch & 15) * 8;
            cp16(sbase + (u32)(R_A + r * RPAD + co) * 2,
                 hsrc + (size_t)r * H_SZ + kc * 128 + co);
        }
        CP_COMMIT(); CP_WAIT0();
        __syncthreads();

        float acc[4][4];
#pragma unroll
        for (int j = 0; j < 4; j++)
#pragma unroll
            for (int v = 0; v < 4; v++) acc[j][v] = 0.f;

#pragma unroll
        for (int ks = 0; ks < 8; ks++) {
            const int k0 = ks * 16;
            u32 a[4], bhi[4][2], blo[4][2];
            {
                u32 off = (u32)((wm * 16 + a_row) * RPAD + k0 + a_kq * 8) * 2;
                ldmx4(a[0], a[1], a[2], a[3], sbase + R_A * 2 + off);
            }
#pragma unroll
            for (int ni = 0; ni < 2; ni++) {
                u32 off = (u32)((wn * 32 + ni * 16 + b_nr) * RPAD + k0 + b_kq * 8) * 2;
                ldmx4(bhi[2*ni][0], bhi[2*ni][1], bhi[2*ni+1][0], bhi[2*ni+1][1],
                      sbase + R_WHI * 2 + off);
                ldmx4(blo[2*ni][0], blo[2*ni][1], blo[2*ni+1][0], blo[2*ni+1][1],
                      sbase + R_WLO * 2 + off);
            }
#pragma unroll
            for (int j = 0; j < 4; j++) {
                mma_f16(acc[j], a, bhi[j]);
                mma_f16(acc[j], a, blo[j]);
            }
        }

        // partial store
        {
            float* p0 = parts + (size_t)kc * BH
                      + (size_t)(wm * 16 + gid) * H_SZ + ct * 64 + wn * 32;
            float* p1 = p0 + 8 * H_SZ;
#pragma unroll
            for (int j = 0; j < 4; j++) {
                *(float2*)(p0 + j * 8 + qid * 2) = make_float2(acc[j][0], acc[j][1]);
                *(float2*)(p1 + j * 8 + qid * 2) = make_float2(acc[j][2], acc[j][3]);
            }
        }

        __threadfence();
        asm volatile("barrier.cluster.arrive.aligned;" ::: "memory");
        asm volatile("barrier.cluster.wait.aligned;"   ::: "memory");

        // in-cluster reduce + tanh + fp16 store
        {
            float2 a2 = aacc;
#pragma unroll
            for (int p = 0; p < KSPLIT; p++) {
                float2 q = __ldcg((const float2*)(parts + (size_t)p * BH + red_off));
                a2.x += q.x; a2.y += q.y;
            }
            a2.x = tanhf(a2.x); a2.y = tanhf(a2.y);

            __half h0 = __float2half_rn(a2.x), h1 = __float2half_rn(a2.y);
            u32 packed = (u32)__half_as_ushort(h0) | ((u32)__half_as_ushort(h1) << 16);
            *(u32*)(g_hsf + (size_t)t * BH + red_off) = packed;

            if (hid_out && t == T_STEPS - 1)
                *(float2*)(hid_out + red_off) = a2;
        }

        __threadfence();
        __syncthreads();
        if (tid == 0)
            *(volatile u32*)&g_stepf[ct][kc] = (u32)(t + 1);
    }

    grid_barrier(0);
    if (blockIdx.x == 0 && tid < 128) {
        ((u32*)g_stepf)[tid] = 0;
    }
}

// ---------------------------------------------------------------------------
extern "C" void kernel_launch(void* const* d_in, const int* in_sizes, int n_in,
                              void* d_out, int out_size)
{
    const int*   input   = (const int*)  d_in[0];
    const float* hidden0 = (const float*)d_in[1];
    const float* emb     = (const float*)d_in[2];
    const float* Wi      = (const float*)d_in[3];
    const float* bi      = (const float*)d_in[4];
    const float* Wh      = (const float*)d_in[5];
    const float* bh      = (const float*)d_in[6];
    const float* Wo      = (const float*)d_in[7];
    const float* bo      = (const float*)d_in[8];
    float* out = (float*)d_out;

    float* hid_out = (out_size >= M_TOT * O_SZ + BH) ? out + (size_t)M_TOT * O_SZ
                                                     : (float*)0;

    cudaFuncSetAttribute(gemm_f16<0>, cudaFuncAttributeMaxDynamicSharedMemorySize, SMEM_G);
    cudaFuncSetAttribute(gemm_f16<1>, cudaFuncAttributeMaxDynamicSharedMemorySize, SMEM_G);
    cudaFuncSetAttribute(rec_mma,    cudaFuncAttributeMaxDynamicSharedMemorySize, SMEM_REC_BYTES);

    prep_bias<<<4, 256>>>(bi, bh);
    prep_transpose_f16<0><<<dim3(32, 32), 256>>>(Wi);
    prep_transpose_f16<1><<<dim3(32, 32), 256>>>(Wo);
    prep_transpose_f16<2><<<dim3(32, 32), 256>>>(Wh);
    prep_h0<<<64, 256>>>(hidden0);
    prep_gather<<<8192, 256>>>(input, emb);

    gemm_f16<0><<<dim3(8, 128), 256, SMEM_G>>>((const float*)0, (float*)0);
    rec_mma<<<NCTA, 256, SMEM_REC_BYTES>>>(hid_out);
    gemm_f16<1><<<dim3(8, 128), 256, SMEM_G>>>(bo, out);
}

// round 13
// speedup vs baseline: 2.1750x; 1.2658x over previous
#include <cuda_runtime.h>
#include <cuda_fp16.h>
#include <math.h>

#define T_STEPS 256
#define B_SZ    64
#define H_SZ    1024
#define O_SZ    1024
#define BH      (B_SZ * H_SZ)        // 65536
#define M_TOT   (T_STEPS * B_SZ)     // 16384
#define KSPLIT  8                    // recurrence k-split == cluster size
#define NCTA    128
#define PAD     40                   // smem row stride (fp16 elems), big gemms
#define RPAD    136                  // smem row stride (fp16 elems), rec tiles

typedef unsigned long long u64;
typedef unsigned int u32;

__device__ __forceinline__ u32 smem_u32(const void* p) {
    u32 a; asm("{ .reg .u64 t; cvta.to.shared.u64 t, %1; cvt.u32.u64 %0, t; }"
               : "=r"(a) : "l"(p));
    return a;
}

// ---- cp.async helpers ------------------------------------------------------
__device__ __forceinline__ void cp16(u32 dst, const void* src) {
    asm volatile("cp.async.cg.shared.global [%0], [%1], 16;"
                 :: "r"(dst), "l"(src));
}
#define CP_COMMIT() asm volatile("cp.async.commit_group;" ::: "memory")
#define CP_WAIT0()  asm volatile("cp.async.wait_group 0;" ::: "memory")

// ---- mma.sync helpers ------------------------------------------------------
__device__ __forceinline__ void ldmx4(u32& r0, u32& r1, u32& r2, u32& r3, u32 a) {
    asm volatile("ldmatrix.sync.aligned.m8n8.x4.shared.b16 {%0,%1,%2,%3}, [%4];"
                 : "=r"(r0), "=r"(r1), "=r"(r2), "=r"(r3) : "r"(a));
}
__device__ __forceinline__ void mma_f16(float* c, const u32* a, const u32* b) {
    asm volatile(
        "mma.sync.aligned.m16n8k16.row.col.f32.f16.f16.f32 "
        "{%0,%1,%2,%3}, {%4,%5,%6,%7}, {%8,%9}, {%0,%1,%2,%3};"
        : "+f"(c[0]), "+f"(c[1]), "+f"(c[2]), "+f"(c[3])
        : "r"(a[0]), "r"(a[1]), "r"(a[2]), "r"(a[3]), "r"(b[0]), "r"(b[1]));
}

// ---- scratch ---------------------------------------------------------------
__device__ float g_acc[(size_t)M_TOT * H_SZ];      // ix + bi + bh (fp32)
__device__ __half g_A1f[(size_t)M_TOT * H_SZ];     // gathered emb, single fp16
__device__ __half g_hsf[(size_t)M_TOT * H_SZ];     // h states, single fp16
__device__ __half g_h0f[BH];
__device__ __half g_WiThf[(size_t)H_SZ * H_SZ];    // fp16 hi/lo [n][k]
__device__ __half g_WiTlf[(size_t)H_SZ * H_SZ];
__device__ __half g_WoThf[(size_t)H_SZ * O_SZ];
__device__ __half g_WoTlf[(size_t)H_SZ * O_SZ];
__device__ __half g_WhThf[(size_t)H_SZ * H_SZ];
__device__ __half g_WhTlf[(size_t)H_SZ * H_SZ];
__device__ float g_parts[2][(size_t)KSPLIT * BH];  // double-buffered by t&1
__device__ float g_bias1[H_SZ];
__device__ unsigned g_cnt[2];
__device__ unsigned g_flag[2];
__device__ u32 g_stepf[16][8];                     // rec per-(chunk, kc) flags
__device__ u32 g_acc_cnt[128];                     // per-mt K1 completion (8 = done)

// ---------------------------------------------------------------------------
// Prep kernels
// ---------------------------------------------------------------------------
__global__ void prep_bias(const float* __restrict__ bi, const float* __restrict__ bh) {
    int i = blockIdx.x * 256 + threadIdx.x;
    g_bias1[i] = bi[i] + bh[i];
}

// W=0: Wi, W=1: Wo, W=2: Wh -> fp16 hi/lo [n][k]
template<int W>
__global__ void prep_transpose_f16(const float* __restrict__ src) {
    __shared__ float ts[32][33];
    __half* dhi = (W == 0) ? g_WiThf : (W == 1) ? g_WoThf : g_WhThf;
    __half* dlo = (W == 0) ? g_WiTlf : (W == 1) ? g_WoTlf : g_WhTlf;
    int n0 = blockIdx.x * 32, k0 = blockIdx.y * 32;
    int tx = threadIdx.x & 31, ty = threadIdx.x >> 5;
#pragma unroll
    for (int i = 0; i < 4; i++)
        ts[ty + i * 8][tx] = src[(size_t)(k0 + ty + i * 8) * H_SZ + n0 + tx];
    __syncthreads();
#pragma unroll
    for (int i = 0; i < 4; i++) {
        int n = n0 + ty + i * 8;
        float v = ts[tx][ty + i * 8];
        __half h = __float2half_rn(v);
        float r = v - __half2float(h);
        dhi[(size_t)n * H_SZ + k0 + tx] = h;
        dlo[(size_t)n * H_SZ + k0 + tx] = __float2half_rn(r);
    }
}

__global__ void prep_gather(const int* __restrict__ input, const float* __restrict__ emb) {
    size_t g = (size_t)blockIdx.x * 256 + threadIdx.x;
    size_t e = g * 8;
    int m = (int)(e >> 10), k = (int)(e & 1023);
    int t = m >> 6, b = m & 63;
    int row = input[b * T_STEPS + t];
    float4 v0 = *(const float4*)(emb + (size_t)row * H_SZ + k);
    float4 v1 = *(const float4*)(emb + (size_t)row * H_SZ + k + 4);
    __half hh[8] = {__float2half_rn(v0.x), __float2half_rn(v0.y),
                    __float2half_rn(v0.z), __float2half_rn(v0.w),
                    __float2half_rn(v1.x), __float2half_rn(v1.y),
                    __float2half_rn(v1.z), __float2half_rn(v1.w)};
    *(uint4*)(g_A1f + e) = *(uint4*)hh;
}

__global__ void prep_h0(const float* __restrict__ hidden0) {
    size_t e = ((size_t)blockIdx.x * 256 + threadIdx.x) * 4;
    float4 v = *(const float4*)(hidden0 + e);
    __half hh[4] = {__float2half_rn(v.x), __float2half_rn(v.y),
                    __float2half_rn(v.z), __float2half_rn(v.w)};
    *(uint2*)(g_h0f + e) = *(uint2*)hh;
}

// ---------------------------------------------------------------------------
// K3: fp16 2-term mma GEMM (proven), 128x128 CTA tile. Runs after rec.
// ---------------------------------------------------------------------------
#define TILE_BF (128 * PAD)
#define SMEM_G (2 * 3 * TILE_BF * 2)

__global__ __launch_bounds__(256) void gemm_out(const float* __restrict__ bo,
                                                float* __restrict__ out)
{
    extern __shared__ __half smh[];
    const int tid = threadIdx.x, wid = tid >> 5, lane = tid & 31;
    const int nt = blockIdx.x, mt = blockIdx.y;
    const int wm = wid >> 1, wn = wid & 1;

    const __half* srcT[3] = { g_hsf   + (size_t)mt * 128 * H_SZ,
                              g_WoThf + (size_t)nt * 128 * H_SZ,
                              g_WoTlf + (size_t)nt * 128 * H_SZ };

    const int r0 = tid >> 2, q0 = tid & 3;
    const int r1 = r0 + 64;
    const u32 sbase = smem_u32(smh);

#pragma unroll
    for (int t4 = 0; t4 < 3; t4++) {
        const __half* s = srcT[t4];
        u32 d = sbase + (u32)(t4 * TILE_BF) * 2;
        cp16(d + (u32)(r0 * PAD + q0 * 8) * 2, s + (size_t)r0 * H_SZ + q0 * 8);
        cp16(d + (u32)(r1 * PAD + q0 * 8) * 2, s + (size_t)r1 * H_SZ + q0 * 8);
    }
    CP_COMMIT(); CP_WAIT0();
    __syncthreads();

    float acc[2][8][4];
#pragma unroll
    for (int mi = 0; mi < 2; mi++)
#pragma unroll
        for (int j = 0; j < 8; j++)
#pragma unroll
            for (int v = 0; v < 4; v++) acc[mi][j][v] = 0.f;

    const int a_row = lane & 15, a_kq = lane >> 4;
    const int b_nr = (lane >> 4) * 8 + (lane & 7), b_kq = (lane >> 3) & 1;

#pragma unroll 1
    for (int c = 0; c < 32; c++) {
        const int buf = c & 1;
        if (c < 31) {
            const int col0 = (c + 1) * 32;
#pragma unroll
            for (int t4 = 0; t4 < 3; t4++) {
                const __half* s = srcT[t4] + col0;
                u32 d = sbase + (u32)(((buf ^ 1) * 3 + t4) * TILE_BF) * 2;
                cp16(d + (u32)(r0 * PAD + q0 * 8) * 2, s + (size_t)r0 * H_SZ + q0 * 8);
                cp16(d + (u32)(r1 * PAD + q0 * 8) * 2, s + (size_t)r1 * H_SZ + q0 * 8);
            }
            CP_COMMIT();
        }

        const u32 bA = sbase + (u32)(buf * 3) * TILE_BF * 2;
#pragma unroll
        for (int s = 0; s < 2; s++) {
            const int kc0 = s * 16;
            u32 a[2][4], bhi[8][2], blo[8][2];
#pragma unroll
            for (int mi = 0; mi < 2; mi++) {
                u32 off = (u32)((wm * 32 + mi * 16 + a_row) * PAD + kc0 + a_kq * 8) * 2;
                ldmx4(a[mi][0], a[mi][1], a[mi][2], a[mi][3], bA + 0 * TILE_BF * 2 + off);
            }
#pragma unroll
            for (int ni = 0; ni < 4; ni++) {
                u32 off = (u32)((wn * 64 + ni * 16 + b_nr) * PAD + kc0 + b_kq * 8) * 2;
                ldmx4(bhi[2*ni][0], bhi[2*ni][1], bhi[2*ni+1][0], bhi[2*ni+1][1],
                      bA + 1 * TILE_BF * 2 + off);
                ldmx4(blo[2*ni][0], blo[2*ni][1], blo[2*ni+1][0], blo[2*ni+1][1],
                      bA + 2 * TILE_BF * 2 + off);
            }
#pragma unroll
            for (int mi = 0; mi < 2; mi++)
#pragma unroll
                for (int j = 0; j < 8; j++) {
                    mma_f16(acc[mi][j], a[mi], bhi[j]);
                    mma_f16(acc[mi][j], a[mi], blo[j]);
                }
        }
        if (c < 31) CP_WAIT0();
        __syncthreads();
    }

    const int gid = lane >> 2, qid = lane & 3;
#pragma unroll
    for (int mi = 0; mi < 2; mi++) {
#pragma unroll
        for (int j = 0; j < 8; j++) {
            int col = nt * 128 + wn * 64 + j * 8 + qid * 2;
            float2 bv = *(const float2*)(bo + col);
            int mA = mt * 128 + wm * 32 + mi * 16 + gid;
            int mB = mA + 8;
            float* dA = out + ((size_t)(mA & 63) * T_STEPS + (mA >> 6)) * O_SZ + col;
            float* dB = out + ((size_t)(mB & 63) * T_STEPS + (mB >> 6)) * O_SZ + col;
            *(float2*)dA = make_float2(acc[mi][j][0] + bv.x, acc[mi][j][1] + bv.y);
            *(float2*)dB = make_float2(acc[mi][j][2] + bv.x, acc[mi][j][3] + bv.y);
        }
    }
}

// ---------------------------------------------------------------------------
// Flat grid barrier among the 128 rec CTAs (proven). Used once at rec end.
// ---------------------------------------------------------------------------
__device__ __forceinline__ void grid_barrier(int slot) {
    __syncthreads();
    if (threadIdx.x == 0) {
        volatile unsigned* fl = &g_flag[slot];
        unsigned prev = *fl;
        __threadfence();
        unsigned old = atomicAdd(&g_cnt[slot], 1u);
        if (old == NCTA - 1) {
            atomicExch(&g_cnt[slot], 0u);
            __threadfence();
            atomicAdd(&g_flag[slot], 1u);
        } else {
            while (*fl == prev) { }
        }
        __threadfence();
    }
    __syncthreads();
}

// ---------------------------------------------------------------------------
// MEGA kernel: blocks 0..127 = persistent clustered recurrence (R12-proven),
// blocks 128..1151 = K1 tiles (gemm_f16<0> body) publishing g_acc_cnt[mt].
// Rec waits g_acc_cnt[t>>1]==8 before consuming g_acc[t]. K1 waits on
// nothing -> no circular dependency -> deadlock-free.
// ---------------------------------------------------------------------------
#define R_WHI 0
#define R_WLO (64 * RPAD)
#define R_A   (2 * 64 * RPAD)
#define SMEM_REC_BYTES (3 * 64 * RPAD * 2)
#define SMEM_MEGA (SMEM_G > SMEM_REC_BYTES ? SMEM_G : SMEM_REC_BYTES)

__device__ __forceinline__ void rec_body(char* rsm_c, float* __restrict__ hid_out)
{
    __half* rsh = (__half*)rsm_c;
    const int tid = threadIdx.x, wid = tid >> 5, lane = tid & 31;
    const int ct  = blockIdx.x >> 3;
    const int kc  = blockIdx.x & 7;
    const int wm  = wid >> 1, wn = wid & 1;

    // one-time Wh tile load: rows n = ct*64 .. +64, cols k = kc*128 .. +128
    {
        const size_t base = (size_t)(ct * 64) * H_SZ + kc * 128;
#pragma unroll
        for (int i = 0; i < 4; i++) {
            int ch = tid + i * 256;
            int r  = ch >> 4;
            int co = (ch & 15) * 8;
            *(uint4*)(rsh + R_WHI + r * RPAD + co) =
                *(const uint4*)(g_WhThf + base + (size_t)r * H_SZ + co);
            *(uint4*)(rsh + R_WLO + r * RPAD + co) =
                *(const uint4*)(g_WhTlf + base + (size_t)r * H_SZ + co);
        }
    }

    const u32 sbase = smem_u32(rsh);
    const int a_row = lane & 15, a_kq = lane >> 4;
    const int b_nr = (lane >> 4) * 8 + (lane & 7), b_kq = (lane >> 3) & 1;
    const int gid = lane >> 2, qid = lane & 3;

    const int red_row = kc * 8 + (tid >> 5);
    const size_t red_off = (size_t)red_row * H_SZ + ct * 64 + (tid & 31) * 2;

    volatile u32* myflag = (tid < 16)
        ? &g_stepf[2 * kc + (tid >> 3)][tid & 7] : (volatile u32*)0;

#pragma unroll 1
    for (int t = 0; t < T_STEPS; t++) {
        const __half* hsrc = t ? (g_hsf + (size_t)(t - 1) * BH) : g_h0f;
        float* parts = g_parts[t & 1];

        // wait producers: h flags (t>0) and the K1 acc tile for this t
        if (tid == 0) {
            volatile u32* ac = &g_acc_cnt[t >> 1];
            while (*ac < 8u) { }
            __threadfence();
        }
        if (t > 0 && tid < 16) {
            while (*myflag < (u32)t) { }
            __threadfence();
        }
        __syncthreads();

        // pre-activation for the reduce (L2 read; K1 wrote it this kernel)
        float2 aacc = __ldcg((const float2*)(g_acc + (size_t)t * BH + red_off));

        // stage h slice (64 x 128 fp16 = 16KB) via cp.async
#pragma unroll
        for (int i = 0; i < 4; i++) {
            int ch = tid + i * 256;
            int r  = ch >> 4;
            int co = (ch & 15) * 8;
            cp16(sbase + (u32)(R_A + r * RPAD + co) * 2,
                 hsrc + (size_t)r * H_SZ + kc * 128 + co);
        }
        CP_COMMIT(); CP_WAIT0();
        __syncthreads();

        float acc[4][4];
#pragma unroll
        for (int j = 0; j < 4; j++)
#pragma unroll
            for (int v = 0; v < 4; v++) acc[j][v] = 0.f;

#pragma unroll
        for (int ks = 0; ks < 8; ks++) {
            const int k0 = ks * 16;
            u32 a[4], bhi[4][2], blo[4][2];
            {
                u32 off = (u32)((wm * 16 + a_row) * RPAD + k0 + a_kq * 8) * 2;
                ldmx4(a[0], a[1], a[2], a[3], sbase + R_A * 2 + off);
            }
#pragma unroll
            for (int ni = 0; ni < 2; ni++) {
                u32 off = (u32)((wn * 32 + ni * 16 + b_nr) * RPAD + k0 + b_kq * 8) * 2;
                ldmx4(bhi[2*ni][0], bhi[2*ni][1], bhi[2*ni+1][0], bhi[2*ni+1][1],
                      sbase + R_WHI * 2 + off);
                ldmx4(blo[2*ni][0], blo[2*ni][1], blo[2*ni+1][0], blo[2*ni+1][1],
                      sbase + R_WLO * 2 + off);
            }
#pragma unroll
            for (int j = 0; j < 4; j++) {
                mma_f16(acc[j], a, bhi[j]);
                mma_f16(acc[j], a, blo[j]);
            }
        }

        // partial store
        {
            float* p0 = parts + (size_t)kc * BH
                      + (size_t)(wm * 16 + gid) * H_SZ + ct * 64 + wn * 32;
            float* p1 = p0 + 8 * H_SZ;
#pragma unroll
            for (int j = 0; j < 4; j++) {
                *(float2*)(p0 + j * 8 + qid * 2) = make_float2(acc[j][0], acc[j][1]);
                *(float2*)(p1 + j * 8 + qid * 2) = make_float2(acc[j][2], acc[j][3]);
            }
        }

        __threadfence();
        asm volatile("barrier.cluster.arrive.aligned;" ::: "memory");
        asm volatile("barrier.cluster.wait.aligned;"   ::: "memory");

        // in-cluster reduce + tanh + fp16 store
        {
            float2 a2 = aacc;
#pragma unroll
            for (int p = 0; p < KSPLIT; p++) {
                float2 q = __ldcg((const float2*)(parts + (size_t)p * BH + red_off));
                a2.x += q.x; a2.y += q.y;
            }
            a2.x = tanhf(a2.x); a2.y = tanhf(a2.y);

            __half h0 = __float2half_rn(a2.x), h1 = __float2half_rn(a2.y);
            u32 packed = (u32)__half_as_ushort(h0) | ((u32)__half_as_ushort(h1) << 16);
            *(u32*)(g_hsf + (size_t)t * BH + red_off) = packed;

            if (hid_out && t == T_STEPS - 1)
                *(float2*)(hid_out + red_off) = a2;
        }

        __threadfence();
        __syncthreads();
        if (tid == 0)
            *(volatile u32*)&g_stepf[ct][kc] = (u32)(t + 1);
    }

    // reset all flags for graph replay (behind the rec-only grid barrier;
    // all K1 CTAs finished earlier since rec consumed acc_cnt[127]==8)
    grid_barrier(0);
    if (blockIdx.x == 0) {
        if (tid < 128) ((u32*)g_stepf)[tid] = 0;
        else if (tid < 256) g_acc_cnt[tid - 128] = 0;
    }
}

__device__ __forceinline__ void k1_body(char* smc)
{
    __half* smh = (__half*)smc;
    const int tid = threadIdx.x, wid = tid >> 5, lane = tid & 31;
    const int idx = blockIdx.x - NCTA;
    const int nt = idx & 7, mt = idx >> 3;
    const int wm = wid >> 1, wn = wid & 1;

    const __half* srcT[3] = { g_A1f   + (size_t)mt * 128 * H_SZ,
                              g_WiThf + (size_t)nt * 128 * H_SZ,
                              g_WiTlf + (size_t)nt * 128 * H_SZ };

    const int r0 = tid >> 2, q0 = tid & 3;
    const int r1 = r0 + 64;
    const u32 sbase = smem_u32(smh);

#pragma unroll
    for (int t4 = 0; t4 < 3; t4++) {
        const __half* s = srcT[t4];
        u32 d = sbase + (u32)(t4 * TILE_BF) * 2;
        cp16(d + (u32)(r0 * PAD + q0 * 8) * 2, s + (size_t)r0 * H_SZ + q0 * 8);
        cp16(d + (u32)(r1 * PAD + q0 * 8) * 2, s + (size_t)r1 * H_SZ + q0 * 8);
    }
    CP_COMMIT(); CP_WAIT0();
    __syncthreads();

    float acc[2][8][4];
#pragma unroll
    for (int mi = 0; mi < 2; mi++)
#pragma unroll
        for (int j = 0; j < 8; j++)
#pragma unroll
            for (int v = 0; v < 4; v++) acc[mi][j][v] = 0.f;

    const int a_row = lane & 15, a_kq = lane >> 4;
    const int b_nr = (lane >> 4) * 8 + (lane & 7), b_kq = (lane >> 3) & 1;

#pragma unroll 1
    for (int c = 0; c < 32; c++) {
        const int buf = c & 1;
        if (c < 31) {
            const int col0 = (c + 1) * 32;
#pragma unroll
            for (int t4 = 0; t4 < 3; t4++) {
                const __half* s = srcT[t4] + col0;
                u32 d = sbase + (u32)(((buf ^ 1) * 3 + t4) * TILE_BF) * 2;
                cp16(d + (u32)(r0 * PAD + q0 * 8) * 2, s + (size_t)r0 * H_SZ + q0 * 8);
                cp16(d + (u32)(r1 * PAD + q0 * 8) * 2, s + (size_t)r1 * H_SZ + q0 * 8);
            }
            CP_COMMIT();
        }

        const u32 bA = sbase + (u32)(buf * 3) * TILE_BF * 2;
#pragma unroll
        for (int s = 0; s < 2; s++) {
            const int kc0 = s * 16;
            u32 a[2][4], bhi[8][2], blo[8][2];
#pragma unroll
            for (int mi = 0; mi < 2; mi++) {
                u32 off = (u32)((wm * 32 + mi * 16 + a_row) * PAD + kc0 + a_kq * 8) * 2;
                ldmx4(a[mi][0], a[mi][1], a[mi][2], a[mi][3], bA + 0 * TILE_BF * 2 + off);
            }
#pragma unroll
            for (int ni = 0; ni < 4; ni++) {
                u32 off = (u32)((wn * 64 + ni * 16 + b_nr) * PAD + kc0 + b_kq * 8) * 2;
                ldmx4(bhi[2*ni][0], bhi[2*ni][1], bhi[2*ni+1][0], bhi[2*ni+1][1],
                      bA + 1 * TILE_BF * 2 + off);
                ldmx4(blo[2*ni][0], blo[2*ni][1], blo[2*ni+1][0], blo[2*ni+1][1],
                      bA + 2 * TILE_BF * 2 + off);
            }
#pragma unroll
            for (int mi = 0; mi < 2; mi++)
#pragma unroll
                for (int j = 0; j < 8; j++) {
                    mma_f16(acc[mi][j], a[mi], bhi[j]);
                    mma_f16(acc[mi][j], a[mi], blo[j]);
                }
        }
        if (c < 31) CP_WAIT0();
        __syncthreads();
    }

    const int gid = lane >> 2, qid = lane & 3;
#pragma unroll
    for (int mi = 0; mi < 2; mi++) {
#pragma unroll
        for (int j = 0; j < 8; j++) {
            int col = nt * 128 + wn * 64 + j * 8 + qid * 2;
            float2 bv = *(const float2*)(g_bias1 + col);
            int mA = mt * 128 + wm * 32 + mi * 16 + gid;
            int mB = mA + 8;
            float* dA = g_acc + (size_t)mA * H_SZ + col;
            float* dB = g_acc + (size_t)mB * H_SZ + col;
            *(float2*)dA = make_float2(acc[mi][j][0] + bv.x, acc[mi][j][1] + bv.y);
            *(float2*)dB = make_float2(acc[mi][j][2] + bv.x, acc[mi][j][3] + bv.y);
        }
    }

    // publish this tile: all 256 threads' stores done, then count it
    __threadfence();
    __syncthreads();
    if (tid == 0) atomicAdd(&g_acc_cnt[mt], 1u);
}

__global__ __launch_bounds__(256, 2) __cluster_dims__(KSPLIT, 1, 1)
void mega(float* __restrict__ hid_out)
{
    extern __shared__ char msm[];
    if (blockIdx.x < NCTA) { rec_body(msm, hid_out); return; }
    k1_body(msm);
}

// ---------------------------------------------------------------------------
extern "C" void kernel_launch(void* const* d_in, const int* in_sizes, int n_in,
                              void* d_out, int out_size)
{
    const int*   input   = (const int*)  d_in[0];
    const float* hidden0 = (const float*)d_in[1];
    const float* emb     = (const float*)d_in[2];
    const float* Wi      = (const float*)d_in[3];
    const float* bi      = (const float*)d_in[4];
    const float* Wh      = (const float*)d_in[5];
    const float* bh      = (const float*)d_in[6];
    const float* Wo      = (const float*)d_in[7];
    const float* bo      = (const float*)d_in[8];
    float* out = (float*)d_out;

    float* hid_out = (out_size >= M_TOT * O_SZ + BH) ? out + (size_t)M_TOT * O_SZ
                                                     : (float*)0;

    cudaFuncSetAttribute(mega,     cudaFuncAttributeMaxDynamicSharedMemorySize, SMEM_MEGA);
    cudaFuncSetAttribute(gemm_out, cudaFuncAttributeMaxDynamicSharedMemorySize, SMEM_G);

    prep_bias<<<4, 256>>>(bi, bh);
    prep_transpose_f16<0><<<dim3(32, 32), 256>>>(Wi);
    prep_transpose_f16<1><<<dim3(32, 32), 256>>>(Wo);
    prep_transpose_f16<2><<<dim3(32, 32), 256>>>(Wh);
    prep_h0<<<64, 256>>>(hidden0);
    prep_gather<<<8192, 256>>>(input, emb);

    mega<<<NCTA + 1024, 256, SMEM_MEGA>>>(hid_out);
    gemm_out<<<dim3(8, 128), 256, SMEM_G>>>(bo, out);
}